// round 1
// baseline (speedup 1.0000x reference)
#include <cuda_runtime.h>

#define B_ 16
#define A_ 5
#define C_ 512
#define HW_ 256
#define NC 4
#define ROWP 264   // 256 + 8 pad (conflict mitigation)
#define CCHUNK 64

// out[(i*B+b)] = local[(i*B+b)] + sum_{j != i, j<n, i<n} warp(local[(j*B+b)], trans[b,i,j])
// warp = grid_sample(grid_sample(img, rot_grid), trans_grid), bilinear, zero pad, align_corners=False.
// Geometry is channel-invariant -> per-thread tap tables in registers, reused over all channels.

__global__ __launch_bounds__(256, 2)
void fuse_kernel(const float* __restrict__ feat,
                 const float* __restrict__ trans,
                 const int* __restrict__ nag,
                 float* __restrict__ out)
{
    __shared__ float tileA[NC][ROWP];  // source channel tiles of neighbor j
    __shared__ float tileR[NC][ROWP];  // rotation-sampled intermediate

    const int b  = blockIdx.z;
    const int i  = blockIdx.y;
    const int c0 = blockIdx.x * CCHUNK;
    const int t  = threadIdx.x;
    const int x  = t & 15;
    const int y  = t >> 4;

    const int n = nag[b * A_];            // num_agent_tensor[b, 0] (int32)
    const bool active = (i < n) && (n > 1);

    const size_t base = ((size_t)(i * B_ + b) * C_ + c0) * HW_;
    const float* __restrict__ local = feat + base;
    float* __restrict__ outp        = out  + base;

    // normalized pixel coords (align_corners=False)
    const float xs = (2.f * (float)x + 1.f) / 16.f - 1.f;
    const float ys = (2.f * (float)y + 1.f) / 16.f - 1.f;

    // Per-neighbor tap metadata (channel-invariant). Slot jj enumerates j != i.
    float wA[4][4];  int iA[4][4];   // stage 1: rotation bilinear taps into source tile
    float wB[4][4];  int iB[4][4];   // stage 2: translation bilinear taps into R tile
    const float* srcp[4];
    bool valid[4];

    #pragma unroll
    for (int jj = 0; jj < 4; jj++) {
        const int j = jj + (jj >= i ? 1 : 0);          // skip j == i
        const bool v = active && (j < n);
        valid[jj] = v;
        srcp[jj]  = feat + ((size_t)(j * B_ + b) * C_ + c0) * HW_;
        #pragma unroll
        for (int m = 0; m < 4; m++) { wA[jj][m] = 0.f; iA[jj][m] = 0; wB[jj][m] = 0.f; iB[jj][m] = 0; }
        if (v) {
            const float* T = trans + (((size_t)(b * A_ + i) * A_ + j) * 16);
            const float t00 = T[0], t01 = T[1], t03 = T[3];
            const float t10 = T[4], t11 = T[5], t13 = T[7];

            // ---- stage 1: rotation grid ----
            const float gx = t00 * xs + t01 * ys;
            const float gy = t10 * xs + t11 * ys;
            const float ix = ((gx + 1.f) * 16.f - 1.f) * 0.5f;
            const float iy = ((gy + 1.f) * 16.f - 1.f) * 0.5f;
            const float x0f = floorf(ix), y0f = floorf(iy);
            const float fx = ix - x0f,  fy = iy - y0f;
            const int x0 = (int)x0f, y0 = (int)y0f;
            #pragma unroll
            for (int m = 0; m < 4; m++) {
                const int dx = m & 1, dy = m >> 1;
                const int xi = x0 + dx, yi = y0 + dy;
                const float w = (dx ? fx : 1.f - fx) * (dy ? fy : 1.f - fy);
                const bool in = (xi >= 0) & (xi < 16) & (yi >= 0) & (yi < 16);
                wA[jj][m] = in ? w : 0.f;
                iA[jj][m] = in ? (yi * 16 + xi) : 0;
            }

            // ---- stage 2: translation grid ----
            const float xt = t03 * (1.f / 32.f);      // 4*T03/128
            const float yt = -t13 * (1.f / 32.f);
            const float gx2 = xs + xt;
            const float gy2 = ys + yt;
            const float ix2 = ((gx2 + 1.f) * 16.f - 1.f) * 0.5f;
            const float iy2 = ((gy2 + 1.f) * 16.f - 1.f) * 0.5f;
            const float x20f = floorf(ix2), y20f = floorf(iy2);
            const float fx2 = ix2 - x20f,  fy2 = iy2 - y20f;
            const int x20 = (int)x20f, y20 = (int)y20f;
            #pragma unroll
            for (int m = 0; m < 4; m++) {
                const int dx = m & 1, dy = m >> 1;
                const int xi = x20 + dx, yi = y20 + dy;
                const float w = (dx ? fx2 : 1.f - fx2) * (dy ? fy2 : 1.f - fy2);
                const bool in = (xi >= 0) & (xi < 16) & (yi >= 0) & (yi < 16);
                wB[jj][m] = in ? w : 0.f;
                iB[jj][m] = in ? (yi * 16 + xi) : 0;
            }
        }
    }

    for (int g = 0; g < CCHUNK; g += NC) {
        float acc[NC];
        #pragma unroll
        for (int k = 0; k < NC; k++) acc[k] = local[(size_t)(g + k) * HW_ + t];

        #pragma unroll
        for (int jj = 0; jj < 4; jj++) {
            if (!valid[jj]) continue;                  // uniform across the block (i, n only)
            const float* src = srcp[jj] + (size_t)g * HW_;

            __syncthreads();                           // prev iter's tile reads complete
            #pragma unroll
            for (int k = 0; k < NC; k++) tileA[k][t] = src[(size_t)k * HW_ + t];
            __syncthreads();

            // stage 1: rotation sample -> R tile
            #pragma unroll
            for (int k = 0; k < NC; k++) {
                float r = 0.f;
                #pragma unroll
                for (int m = 0; m < 4; m++) r += wA[jj][m] * tileA[k][iA[jj][m]];
                tileR[k][t] = r;
            }
            __syncthreads();

            // stage 2: translation sample -> accumulate
            #pragma unroll
            for (int k = 0; k < NC; k++) {
                #pragma unroll
                for (int m = 0; m < 4; m++) acc[k] += wB[jj][m] * tileR[k][iB[jj][m]];
            }
        }

        #pragma unroll
        for (int k = 0; k < NC; k++) outp[(size_t)(g + k) * HW_ + t] = acc[k];
    }
}

extern "C" void kernel_launch(void* const* d_in, const int* in_sizes, int n_in,
                              void* d_out, int out_size)
{
    const float* feat  = (const float*)d_in[0];   // [A*B, C, H, W] f32
    const float* trans = (const float*)d_in[1];   // [B, A, A, 4, 4] f32
    const int*   nag   = (const int*)d_in[2];     // [B, A] int32
    float* out = (float*)d_out;                   // [A*B, C, H, W] f32

    dim3 grid(C_ / CCHUNK, A_, B_);
    fuse_kernel<<<grid, 256>>>(feat, trans, nag, out);
}

// round 2
// speedup vs baseline: 1.1881x; 1.1881x over previous
#include <cuda_runtime.h>

#define B_ 16
#define A_ 5
#define C_ 512
#define HW_ 256
#define NC 4
#define ROWP 264   // 256 + 8 pad
#define CCHUNK 32

// out[(i*B+b)] = local[(i*B+b)] + sum_{j != i, j<n, i<n} warp(local[(j*B+b)], trans[b,i,j])
// warp = bilinear grid_sample chained twice (rotation, then constant translation),
// zero padding, align_corners=False. Geometry is channel-invariant -> per-thread
// tap tables in registers (indices byte-packed), reused over all channels.
// All valid neighbors staged per barrier phase: 3 __syncthreads per channel chunk.

__global__ __launch_bounds__(256, 2)
void fuse_kernel(const float* __restrict__ feat,
                 const float* __restrict__ trans,
                 const int* __restrict__ nag,
                 float* __restrict__ out)
{
    __shared__ float tileA[4][NC][ROWP];  // source tiles, all 4 neighbor slots
    __shared__ float tileR[4][NC][ROWP];  // rotation-sampled intermediates

    const int b  = blockIdx.z;
    const int i  = blockIdx.y;
    const int c0 = blockIdx.x * CCHUNK;
    const int t  = threadIdx.x;
    const int x  = t & 15;
    const int y  = t >> 4;

    const int n = nag[b * A_];            // num_agent_tensor[b, 0]
    const bool active = (i < n) && (n > 1);

    const size_t base = ((size_t)(i * B_ + b) * C_ + c0) * HW_;
    const float* __restrict__ local = feat + base;
    float* __restrict__ outp        = out  + base;

    // normalized pixel coords (align_corners=False)
    const float xs = (2.f * (float)x + 1.f) / 16.f - 1.f;
    const float ys = (2.f * (float)y + 1.f) / 16.f - 1.f;

    // Per-neighbor tap metadata (channel-invariant).
    float    wA[4][4], wB[4][4];
    unsigned pA[4], pB[4];                // 4 byte-indices packed per table
    const float* srcp[4];
    bool valid[4];

    #pragma unroll
    for (int jj = 0; jj < 4; jj++) {
        const int j = jj + (jj >= i ? 1 : 0);          // skip j == i
        const bool v = active && (j < n);
        valid[jj] = v;
        srcp[jj]  = feat + ((size_t)(j * B_ + b) * C_ + c0) * HW_;
        pA[jj] = 0u; pB[jj] = 0u;
        #pragma unroll
        for (int m = 0; m < 4; m++) { wA[jj][m] = 0.f; wB[jj][m] = 0.f; }
        if (v) {
            const float* T = trans + (((size_t)(b * A_ + i) * A_ + j) * 16);
            const float t00 = T[0], t01 = T[1], t03 = T[3];
            const float t10 = T[4], t11 = T[5], t13 = T[7];

            // ---- stage 1: rotation grid ----
            const float gx = t00 * xs + t01 * ys;
            const float gy = t10 * xs + t11 * ys;
            const float ix = ((gx + 1.f) * 16.f - 1.f) * 0.5f;
            const float iy = ((gy + 1.f) * 16.f - 1.f) * 0.5f;
            const float x0f = floorf(ix), y0f = floorf(iy);
            const float fx = ix - x0f,  fy = iy - y0f;
            const int x0 = (int)x0f, y0 = (int)y0f;
            #pragma unroll
            for (int m = 0; m < 4; m++) {
                const int dx = m & 1, dy = m >> 1;
                const int xi = x0 + dx, yi = y0 + dy;
                const float w = (dx ? fx : 1.f - fx) * (dy ? fy : 1.f - fy);
                const bool in = (xi >= 0) & (xi < 16) & (yi >= 0) & (yi < 16);
                wA[jj][m] = in ? w : 0.f;
                pA[jj]  |= (unsigned)(in ? (yi * 16 + xi) : 0) << (8 * m);
            }

            // ---- stage 2: translation grid ----
            const float xt = t03 * (1.f / 32.f);      // 4*T03/128
            const float yt = -t13 * (1.f / 32.f);
            const float ix2 = ((xs + xt + 1.f) * 16.f - 1.f) * 0.5f;
            const float iy2 = ((ys + yt + 1.f) * 16.f - 1.f) * 0.5f;
            const float x20f = floorf(ix2), y20f = floorf(iy2);
            const float fx2 = ix2 - x20f,  fy2 = iy2 - y20f;
            const int x20 = (int)x20f, y20 = (int)y20f;
            #pragma unroll
            for (int m = 0; m < 4; m++) {
                const int dx = m & 1, dy = m >> 1;
                const int xi = x20 + dx, yi = y20 + dy;
                const float w = (dx ? fx2 : 1.f - fx2) * (dy ? fy2 : 1.f - fy2);
                const bool in = (xi >= 0) & (xi < 16) & (yi >= 0) & (yi < 16);
                wB[jj][m] = in ? w : 0.f;
                pB[jj]  |= (unsigned)(in ? (yi * 16 + xi) : 0) << (8 * m);
            }
        }
    }

    for (int g = 0; g < CCHUNK; g += NC) {
        float acc[NC];
        #pragma unroll
        for (int k = 0; k < NC; k++) acc[k] = local[(size_t)(g + k) * HW_ + t];

        __syncthreads();                           // prev iter's tileR reads complete
        #pragma unroll
        for (int jj = 0; jj < 4; jj++) {
            if (valid[jj]) {                       // uniform across block
                const float* src = srcp[jj] + (size_t)g * HW_;
                #pragma unroll
                for (int k = 0; k < NC; k++) tileA[jj][k][t] = src[(size_t)k * HW_ + t];
            }
        }
        __syncthreads();

        // stage 1: rotation sample -> R tiles (all neighbors)
        #pragma unroll
        for (int jj = 0; jj < 4; jj++) {
            if (valid[jj]) {
                int ia0 = (pA[jj]      ) & 255;
                int ia1 = (pA[jj] >>  8) & 255;
                int ia2 = (pA[jj] >> 16) & 255;
                int ia3 = (pA[jj] >> 24) & 255;
                #pragma unroll
                for (int k = 0; k < NC; k++) {
                    float r = wA[jj][0] * tileA[jj][k][ia0]
                            + wA[jj][1] * tileA[jj][k][ia1]
                            + wA[jj][2] * tileA[jj][k][ia2]
                            + wA[jj][3] * tileA[jj][k][ia3];
                    tileR[jj][k][t] = r;
                }
            }
        }
        __syncthreads();

        // stage 2: translation sample -> accumulate (all neighbors)
        #pragma unroll
        for (int jj = 0; jj < 4; jj++) {
            if (valid[jj]) {
                int ib0 = (pB[jj]      ) & 255;
                int ib1 = (pB[jj] >>  8) & 255;
                int ib2 = (pB[jj] >> 16) & 255;
                int ib3 = (pB[jj] >> 24) & 255;
                #pragma unroll
                for (int k = 0; k < NC; k++) {
                    acc[k] += wB[jj][0] * tileR[jj][k][ib0]
                            + wB[jj][1] * tileR[jj][k][ib1]
                            + wB[jj][2] * tileR[jj][k][ib2]
                            + wB[jj][3] * tileR[jj][k][ib3];
                }
            }
        }

        #pragma unroll
        for (int k = 0; k < NC; k++) outp[(size_t)(g + k) * HW_ + t] = acc[k];
    }
}

extern "C" void kernel_launch(void* const* d_in, const int* in_sizes, int n_in,
                              void* d_out, int out_size)
{
    const float* feat  = (const float*)d_in[0];   // [A*B, C, H, W] f32
    const float* trans = (const float*)d_in[1];   // [B, A, A, 4, 4] f32
    const int*   nag   = (const int*)d_in[2];     // [B, A] int32
    float* out = (float*)d_out;                   // [A*B, C, H, W] f32

    dim3 grid(C_ / CCHUNK, A_, B_);
    fuse_kernel<<<grid, 256>>>(feat, trans, nag, out);
}

// round 4
// speedup vs baseline: 1.3282x; 1.1179x over previous
#include <cuda_runtime.h>

#define B_ 16
#define A_ 5
#define C_ 512
#define HW_ 256
#define NC 4
#define CCHUNK 32

// out[(i*B+b)] = local[(i*B+b)] + sum_{j != i, j<n, i<n} warp(local[(j*B+b)], trans[b,i,j])
// warp = bilinear grid_sample chained twice (rotation, then constant translation),
// zero padding, align_corners=False. Geometry is channel-invariant -> per-thread
// tap tables in registers. Tiles are channel-vectorized float4 ([pixel][4ch]) so
// each bilinear tap is a single LDS.128 covering 4 channels.

__global__ __launch_bounds__(256, 2)
void fuse_kernel(const float* __restrict__ feat,
                 const float* __restrict__ trans,
                 const int* __restrict__ nag,
                 float* __restrict__ out)
{
    __shared__ float4 tileA[4][257];   // per neighbor slot: 256 pixels x 4 channels
    __shared__ float4 tileR[4][257];   // rotation-sampled intermediates

    const int b  = blockIdx.z;
    const int i  = blockIdx.y;
    const int c0 = blockIdx.x * CCHUNK;
    const int t  = threadIdx.x;
    const int x  = t & 15;
    const int y  = t >> 4;

    const int n = nag[b * A_];            // num_agent_tensor[b, 0]
    const bool active = (i < n) && (n > 1);

    const size_t base = ((size_t)(i * B_ + b) * C_ + c0) * HW_;
    const float* __restrict__ local = feat + base;
    float* __restrict__ outp        = out  + base;

    // normalized pixel coords (align_corners=False)
    const float xs = (2.f * (float)x + 1.f) / 16.f - 1.f;
    const float ys = (2.f * (float)y + 1.f) / 16.f - 1.f;

    // Per-neighbor tap metadata (channel-invariant).
    float    wA[4][4], wB[4][4];
    unsigned pA[4], pB[4];                // 4 byte-indices packed per table
    const float* srcp[4];
    bool valid[4];

    #pragma unroll
    for (int jj = 0; jj < 4; jj++) {
        const int j = jj + (jj >= i ? 1 : 0);          // skip j == i
        const bool v = active && (j < n);
        valid[jj] = v;
        srcp[jj]  = feat + ((size_t)(j * B_ + b) * C_ + c0) * HW_;
        pA[jj] = 0u; pB[jj] = 0u;
        #pragma unroll
        for (int m = 0; m < 4; m++) { wA[jj][m] = 0.f; wB[jj][m] = 0.f; }
        if (v) {
            const float* T = trans + (((size_t)(b * A_ + i) * A_ + j) * 16);
            const float t00 = T[0], t01 = T[1], t03 = T[3];
            const float t10 = T[4], t11 = T[5], t13 = T[7];

            // ---- stage 1: rotation grid ----
            const float gx = t00 * xs + t01 * ys;
            const float gy = t10 * xs + t11 * ys;
            const float ix = ((gx + 1.f) * 16.f - 1.f) * 0.5f;
            const float iy = ((gy + 1.f) * 16.f - 1.f) * 0.5f;
            const float x0f = floorf(ix), y0f = floorf(iy);
            const float fx = ix - x0f,  fy = iy - y0f;
            const int x0 = (int)x0f, y0 = (int)y0f;
            #pragma unroll
            for (int m = 0; m < 4; m++) {
                const int dx = m & 1, dy = m >> 1;
                const int xi = x0 + dx, yi = y0 + dy;
                const float w = (dx ? fx : 1.f - fx) * (dy ? fy : 1.f - fy);
                const bool in = (xi >= 0) & (xi < 16) & (yi >= 0) & (yi < 16);
                wA[jj][m] = in ? w : 0.f;
                pA[jj]  |= (unsigned)(in ? (yi * 16 + xi) : 0) << (8 * m);
            }

            // ---- stage 2: translation grid ----
            const float xt = t03 * (1.f / 32.f);      // 4*T03/128
            const float yt = -t13 * (1.f / 32.f);
            const float ix2 = ((xs + xt + 1.f) * 16.f - 1.f) * 0.5f;
            const float iy2 = ((ys + yt + 1.f) * 16.f - 1.f) * 0.5f;
            const float x20f = floorf(ix2), y20f = floorf(iy2);
            const float fx2 = ix2 - x20f,  fy2 = iy2 - y20f;
            const int x20 = (int)x20f, y20 = (int)y20f;
            #pragma unroll
            for (int m = 0; m < 4; m++) {
                const int dx = m & 1, dy = m >> 1;
                const int xi = x20 + dx, yi = y20 + dy;
                const float w = (dx ? fx2 : 1.f - fx2) * (dy ? fy2 : 1.f - fy2);
                const bool in = (xi >= 0) & (xi < 16) & (yi >= 0) & (yi < 16);
                wB[jj][m] = in ? w : 0.f;
                pB[jj]  |= (unsigned)(in ? (yi * 16 + xi) : 0) << (8 * m);
            }
        }
    }

    for (int g = 0; g < CCHUNK; g += NC) {
        float4 acc;
        acc.x = local[(size_t)(g + 0) * HW_ + t];
        acc.y = local[(size_t)(g + 1) * HW_ + t];
        acc.z = local[(size_t)(g + 2) * HW_ + t];
        acc.w = local[(size_t)(g + 3) * HW_ + t];

        __syncthreads();                           // prev iter tile reads complete
        #pragma unroll
        for (int jj = 0; jj < 4; jj++) {
            if (valid[jj]) {                       // uniform across block
                const float* src = srcp[jj] + (size_t)g * HW_;
                float4 v;
                v.x = src[t];
                v.y = src[HW_ + t];
                v.z = src[2 * HW_ + t];
                v.w = src[3 * HW_ + t];
                tileA[jj][t] = v;
            }
        }
        __syncthreads();

        // stage 1: rotation sample -> R tiles (one LDS.128 per tap, 4 channels)
        #pragma unroll
        for (int jj = 0; jj < 4; jj++) {
            if (valid[jj]) {
                const float4 v0 = tileA[jj][(pA[jj]      ) & 255];
                const float4 v1 = tileA[jj][(pA[jj] >>  8) & 255];
                const float4 v2 = tileA[jj][(pA[jj] >> 16) & 255];
                const float4 v3 = tileA[jj][(pA[jj] >> 24) & 255];
                const float w0 = wA[jj][0], w1 = wA[jj][1], w2 = wA[jj][2], w3 = wA[jj][3];
                float4 r;
                r.x = w0 * v0.x + w1 * v1.x + w2 * v2.x + w3 * v3.x;
                r.y = w0 * v0.y + w1 * v1.y + w2 * v2.y + w3 * v3.y;
                r.z = w0 * v0.z + w1 * v1.z + w2 * v2.z + w3 * v3.z;
                r.w = w0 * v0.w + w1 * v1.w + w2 * v2.w + w3 * v3.w;
                tileR[jj][t] = r;
            }
        }
        __syncthreads();

        // stage 2: translation sample -> accumulate
        #pragma unroll
        for (int jj = 0; jj < 4; jj++) {
            if (valid[jj]) {
                const float4 v0 = tileR[jj][(pB[jj]      ) & 255];
                const float4 v1 = tileR[jj][(pB[jj] >>  8) & 255];
                const float4 v2 = tileR[jj][(pB[jj] >> 16) & 255];
                const float4 v3 = tileR[jj][(pB[jj] >> 24) & 255];
                const float w0 = wB[jj][0], w1 = wB[jj][1], w2 = wB[jj][2], w3 = wB[jj][3];
                acc.x += w0 * v0.x + w1 * v1.x + w2 * v2.x + w3 * v3.x;
                acc.y += w0 * v0.y + w1 * v1.y + w2 * v2.y + w3 * v3.y;
                acc.z += w0 * v0.z + w1 * v1.z + w2 * v2.z + w3 * v3.z;
                acc.w += w0 * v0.w + w1 * v1.w + w2 * v2.w + w3 * v3.w;
            }
        }

        outp[(size_t)(g + 0) * HW_ + t] = acc.x;
        outp[(size_t)(g + 1) * HW_ + t] = acc.y;
        outp[(size_t)(g + 2) * HW_ + t] = acc.z;
        outp[(size_t)(g + 3) * HW_ + t] = acc.w;
    }
}

extern "C" void kernel_launch(void* const* d_in, const int* in_sizes, int n_in,
                              void* d_out, int out_size)
{
    const float* feat  = (const float*)d_in[0];   // [A*B, C, H, W] f32
    const float* trans = (const float*)d_in[1];   // [B, A, A, 4, 4] f32
    const int*   nag   = (const int*)d_in[2];     // [B, A] int32
    float* out = (float*)d_out;                   // [A*B, C, H, W] f32

    dim3 grid(C_ / CCHUNK, A_, B_);
    fuse_kernel<<<grid, 256>>>(feat, trans, nag, out);
}